// round 12
// baseline (speedup 1.0000x reference)
#include <cuda_runtime.h>
#include <cuda_bf16.h>
#include <cstdint>

// ---------------------------------------------------------------------------
// Problem constants
// ---------------------------------------------------------------------------
#define NWIN      2048
#define HEADS     8
#define WS2       64
#define HEAD_DIM  32
#define DIMC      256
#define SCALE_F   0.17677669529663687f

// Scratch (static device globals — allocation-free per harness rules)
__device__ unsigned int   g_xhi32[16777216];   // bf16 pairs of x / attn out [row][k/2]
__device__ unsigned int   g_xlo32[16777216];
__device__ unsigned int   g_qkhi[33554432];    // Q,K bf16-hi pairs [part][g][h][t][d/2]
__device__ unsigned int   g_qklo[33554432];
__device__ unsigned short g_vthi16[33554432];  // V^T bf16 [g][h][d][t]
__device__ unsigned short g_vtlo16[33554432];
__device__ unsigned short g_wqhi[196608];      // w_qkv row-major bf16 hi/lo [768][256]
__device__ unsigned short g_wqlo[196608];
__device__ unsigned short g_wohi[65536];       // w_out  row-major bf16 hi/lo [256][256]
__device__ unsigned short g_wolo[65536];

// ---------------------------------------------------------------------------
// Helpers (plain-target PTX only: ldmatrix / mma.sync / cp.async)
// ---------------------------------------------------------------------------
__device__ __forceinline__ uint32_t smem_u32(const void* p) {
    uint32_t a;
    asm("{ .reg .u64 t; cvta.to.shared.u64 t, %1; cvt.u32.u64 %0, t; }" : "=r"(a) : "l"(p));
    return a;
}
__device__ __forceinline__ void cp16(uint32_t dst, const void* src) {
    asm volatile("cp.async.cg.shared.global [%0], [%1], 16;" :: "r"(dst), "l"(src));
}
#define CP_COMMIT()  asm volatile("cp.async.commit_group;")
#define CP_WAIT(n)   asm volatile("cp.async.wait_group %0;" :: "n"(n))

#define LDM4(r, addr) \
    asm volatile("ldmatrix.sync.aligned.m8n8.x4.shared.b16 {%0,%1,%2,%3}, [%4];" \
        : "=r"((r)[0]), "=r"((r)[1]), "=r"((r)[2]), "=r"((r)[3]) : "r"(addr))

#define MMA16816(c, a, b0, b1) \
    asm volatile("mma.sync.aligned.m16n8k16.row.col.f32.bf16.bf16.f32 " \
        "{%0,%1,%2,%3},{%4,%5,%6,%7},{%8,%9},{%0,%1,%2,%3};" \
        : "+f"((c)[0]), "+f"((c)[1]), "+f"((c)[2]), "+f"((c)[3]) \
        : "r"((a)[0]), "r"((a)[1]), "r"((a)[2]), "r"((a)[3]), "r"(b0), "r"(b1))

__device__ __forceinline__ unsigned short bf_hi(float f) {
    return __bfloat16_as_ushort(__float2bfloat16_rn(f));
}
__device__ __forceinline__ uint32_t pack2(float a, float b) {
    return (uint32_t)bf_hi(a) | ((uint32_t)bf_hi(b) << 16);
}

// ---------------------------------------------------------------------------
// prep_x: split fp32 -> bf16 hi/lo packed-pair arrays (4 floats/thread)
// ---------------------------------------------------------------------------
__global__ __launch_bounds__(256) void prep_x_kernel(const float4* __restrict__ x4)
{
    const int gid = blockIdx.x * 256 + threadIdx.x;   // 8,388,608
    const float4 v = x4[gid];
    __nv_bfloat16 h0 = __float2bfloat16_rn(v.x), h1 = __float2bfloat16_rn(v.y);
    __nv_bfloat16 h2 = __float2bfloat16_rn(v.z), h3 = __float2bfloat16_rn(v.w);
    uint2 H, L;
    H.x = (uint32_t)__bfloat16_as_ushort(h0) | ((uint32_t)__bfloat16_as_ushort(h1) << 16);
    H.y = (uint32_t)__bfloat16_as_ushort(h2) | ((uint32_t)__bfloat16_as_ushort(h3) << 16);
    L.x = (uint32_t)bf_hi(v.x - __bfloat162float(h0)) | ((uint32_t)bf_hi(v.y - __bfloat162float(h1)) << 16);
    L.y = (uint32_t)bf_hi(v.z - __bfloat162float(h2)) | ((uint32_t)bf_hi(v.w - __bfloat162float(h3)) << 16);
    ((uint2*)g_xhi32)[gid] = H;
    ((uint2*)g_xlo32)[gid] = L;
}

// ---------------------------------------------------------------------------
// prep_w: weights -> row-major bf16 hi/lo
// ---------------------------------------------------------------------------
__global__ __launch_bounds__(256) void prep_w_kernel(const float* __restrict__ wq,
                                                     const float* __restrict__ wo)
{
    const int idx = blockIdx.x * 256 + threadIdx.x;   // 262,144
    if (idx < 196608) {
        const float v = wq[idx];
        __nv_bfloat16 h = __float2bfloat16_rn(v);
        g_wqhi[idx] = __bfloat16_as_ushort(h);
        g_wqlo[idx] = bf_hi(v - __bfloat162float(h));
    } else {
        const int i2 = idx - 196608;
        const float v = wo[i2];
        __nv_bfloat16 h = __float2bfloat16_rn(v);
        g_wohi[i2] = __bfloat16_as_ushort(h);
        g_wolo[i2] = bf_hi(v - __bfloat162float(h));
    }
}

// ---------------------------------------------------------------------------
// Resident-A HMMA GEMM: one block per 128-row group (grid = 1024).
// A (hi/lo, full K=256) staged ONCE into 160KB smem; nt loop inside the
// kernel streams B through a 40KB double buffer (B is L2-resident).
// 3-term bf16 split; fragment patterns identical to the proven R10 kernel.
// MODE 0: A = x (roll gather), NT=6, C -> bf16 hi/lo Q,K pairs + V transposed
// MODE 1: A = attn out,        NT=2, C -> d_out fp32 (inverse-roll scatter)
// smem: A hi [0,81920) 8 chunks*10240; A lo [81920,163840); B dbuf
//       [163840,204800) = 2 * (hi 10240 + lo 10240).
// ---------------------------------------------------------------------------
#define AB_LO     81920
#define BB_BASE   163840
#define SMEM_BIG  204800

template <int MODE>
__global__ __launch_bounds__(256)
void gemm_big_kernel(const float* __restrict__ bias, float* __restrict__ out)
{
    constexpr int NT = (MODE == 0) ? 6 : 2;
    extern __shared__ char smem[];
    __shared__ int   rowoff[128];
    __shared__ float bias_s[NT * 128];

    const uint32_t sb  = smem_u32(smem);
    const int tid  = threadIdx.x;
    const int wid  = tid >> 5;
    const int lane = tid & 31;
    const int mb   = blockIdx.x;

    if (tid < 128) {
        const int r = tid;
        const int g = mb * 2 + (r >> 6);
        const int b = g >> 6, w = g & 63;
        const int wy = w >> 3, wx = w & 7, ty = (r >> 3) & 7, tx = r & 7;
        const int i_ = (wy * 8 + ty + 4) & 63;
        const int j_ = (wx * 8 + tx + 4) & 63;
        const int srcRow = b * 4096 + i_ * 64 + j_;
        rowoff[r] = (MODE == 0) ? srcRow * 128 : srcRow * 256;
    }
    for (int i = tid; i < NT * 128; i += 256) bias_s[i] = bias[i];
    __syncthreads();

    const unsigned short* wh = (MODE == 0) ? g_wqhi : g_wohi;
    const unsigned short* wl = (MODE == 0) ? g_wqlo : g_wolo;

    const int lrow = tid >> 1;               // 0..127 (2 threads per row)
    const int q0   = (tid & 1) * 2;          // quad pair
    const int aRowBase = (MODE == 0) ? rowoff[lrow] : (mb * 128 + lrow) * 128;  // uint idx

    // ---- stage ALL of A (hi + lo), 8 chunks of k32 ----
#pragma unroll
    for (int kc = 0; kc < 8; kc++) {
#pragma unroll
        for (int j = 0; j < 2; j++) {
            const int q = q0 + j;
            cp16(sb + kc * 10240 + lrow * 80 + q * 16,
                 g_xhi32 + aRowBase + kc * 16 + q * 4);
            cp16(sb + AB_LO + kc * 10240 + lrow * 80 + q * 16,
                 g_xlo32 + aRowBase + kc * 16 + q * 4);
        }
    }
    CP_COMMIT();

#define LOAD_B(nt_, kc_, buf_) do { \
    const uint32_t d = sb + BB_BASE + (buf_) * 20480 + lrow * 80; \
    const int br = ((nt_) * 128 + lrow) * 256 + (kc_) * 32; \
    _Pragma("unroll") \
    for (int j = 0; j < 2; j++) { \
        const int q = q0 + j; \
        cp16(d + q * 16,         wh + br + q * 8); \
        cp16(d + 10240 + q * 16, wl + br + q * 8); \
    } \
} while (0)

    LOAD_B(0, 0, 0);
    CP_COMMIT();
    CP_WAIT(0);
    __syncthreads();

    const int a_off = ((lane & 7) + ((lane >> 3) & 1) * 8) * 80 + (lane >> 4) * 16;
    const int b_off = ((lane & 7) + ((lane >> 3) >> 1) * 8) * 80 + ((lane >> 3) & 1) * 16;
    const int wr = wid & 3;      // 32-row warp block
    const int wc = wid >> 2;     // 64-col warp block

#pragma unroll 1
    for (int nt = 0; nt < NT; nt++) {
        float acc[2][8][4];
#pragma unroll
        for (int i = 0; i < 2; i++)
#pragma unroll
            for (int j = 0; j < 8; j++)
#pragma unroll
                for (int e = 0; e < 4; e++) acc[i][j][e] = 0.f;

#pragma unroll 1
        for (int kc = 0; kc < 8; kc++) {
            const int s = nt * 8 + kc;
            if (s < NT * 8 - 1) {
                const int s1 = s + 1;
                LOAD_B(s1 >> 3, s1 & 7, s1 & 1);
                CP_COMMIT();
                CP_WAIT(1);
            } else {
                CP_WAIT(0);
            }
            __syncthreads();

            const uint32_t Ab = sb + kc * 10240;               // hi; lo at +AB_LO
            const uint32_t Bb = sb + BB_BASE + (s & 1) * 20480; // hi; lo at +10240
#pragma unroll
            for (int ks = 0; ks < 2; ks++) {
                uint32_t ah[2][4], al[2][4];
#pragma unroll
                for (int mt = 0; mt < 2; mt++) {
                    const uint32_t ad = Ab + (wr * 32 + mt * 16) * 80 + ks * 32 + a_off;
                    LDM4(ah[mt], ad);
                    LDM4(al[mt], ad + AB_LO);
                }
#pragma unroll
                for (int np = 0; np < 4; np++) {
                    uint32_t bh[4], bl[4];
                    const uint32_t bd = Bb + (wc * 64 + np * 16) * 80 + ks * 32 + b_off;
                    LDM4(bh, bd);
                    LDM4(bl, bd + 10240);
#pragma unroll
                    for (int mt = 0; mt < 2; mt++) {
#pragma unroll
                        for (int sub = 0; sub < 2; sub++) {
                            float* c = acc[mt][np * 2 + sub];
                            MMA16816(c, ah[mt], bh[2 * sub], bh[2 * sub + 1]);
                            MMA16816(c, ah[mt], bl[2 * sub], bl[2 * sub + 1]);
                            MMA16816(c, al[mt], bh[2 * sub], bh[2 * sub + 1]);
                        }
                    }
                }
            }
            __syncthreads();
        }

        // ---- epilogue for this nt tile ----
#pragma unroll
        for (int mt = 0; mt < 2; mt++) {
            const int R0 = wr * 32 + mt * 16 + (lane >> 2);
#pragma unroll
            for (int nti = 0; nti < 8; nti++) {
                const int cb = wc * 64 + nti * 8 + (lane & 3) * 2;
                const float bz0 = bias_s[nt * 128 + cb], bz1 = bias_s[nt * 128 + cb + 1];
                const float* c = acc[mt][nti];
#pragma unroll
                for (int half = 0; half < 2; half++) {
                    const int R = R0 + half * 8;
                    const float vx = c[half * 2 + 0] + bz0;
                    const float vy = c[half * 2 + 1] + bz1;
                    if (MODE == 0) {
                        const int nn   = nt * 128 + cb;
                        const int part = nn >> 8;
                        const int h    = (nn & 255) >> 5;
                        const int d    = nn & 31;
                        const int g    = mb * 2 + (R >> 6);
                        const int t    = R & 63;
                        __nv_bfloat16 h0 = __float2bfloat16_rn(vx);
                        __nv_bfloat16 h1 = __float2bfloat16_rn(vy);
                        const unsigned short l0 = bf_hi(vx - __bfloat162float(h0));
                        const unsigned short l1 = bf_hi(vy - __bfloat162float(h1));
                        if (part < 2) {
                            const size_t idx = (size_t)part * 16777216 +
                                (((size_t)(g * 8 + h)) * 64 + t) * 16 + (d >> 1);
                            g_qkhi[idx] = (uint32_t)__bfloat16_as_ushort(h0) |
                                          ((uint32_t)__bfloat16_as_ushort(h1) << 16);
                            g_qklo[idx] = (uint32_t)l0 | ((uint32_t)l1 << 16);
                        } else {
                            const size_t bidx = (((size_t)(g * 8 + h)) * 32 + d) * 64 + t;
                            g_vthi16[bidx]      = __bfloat16_as_ushort(h0);
                            g_vthi16[bidx + 64] = __bfloat16_as_ushort(h1);
                            g_vtlo16[bidx]      = l0;
                            g_vtlo16[bidx + 64] = l1;
                        }
                    } else {
                        float2 v;
                        v.x = vx; v.y = vy;
                        *(float2*)(out + rowoff[R] + nt * 128 + cb) = v;
                    }
                }
            }
        }
    }
#undef LOAD_B
}

// ---------------------------------------------------------------------------
// Attention core (HMMA, unchanged from R10 — passing, 3 CTAs/SM)
// ---------------------------------------------------------------------------
#define AT_HEAD_B   29696
#define AT_PE_OFF   59392
#define AT_SMEM     61440

__global__ __launch_bounds__(256, 3)
void attn_kernel(const float* __restrict__ pos_enc)
{
    extern __shared__ char smem[];
    const uint32_t sb = smem_u32(smem);
    const int tid  = threadIdx.x;
    const int wid  = tid >> 5;
    const int lane = tid & 31;

    const int g  = blockIdx.x >> 2;
    const int hp = blockIdx.x & 3;

#pragma unroll
    for (int it = 0; it < 8; it++) {
        const int i = tid + it * 256;
        const int hd  = i >> 10;
        const int tsr = (i >> 8) & 3;
        const int row = (i >> 2) & 63;
        const int q16 = i & 3;
        const int part = tsr >> 1, prec = tsr & 1;
        const unsigned int* src = (prec ? g_qklo : g_qkhi) + (size_t)part * 16777216 +
            (((size_t)(g * 8 + hp * 2 + hd)) * 64 + row) * 16 + q16 * 4;
        cp16(sb + hd * AT_HEAD_B + tsr * 5120 + row * 80 + q16 * 16, src);
    }
#pragma unroll
    for (int it = 0; it < 4; it++) {
        const int i = tid + it * 256;
        const int hd   = i >> 9;
        const int prec = (i >> 8) & 1;
        const int row  = (i >> 3) & 31;
        const int q    = i & 7;
        const unsigned short* src = (prec ? g_vtlo16 : g_vthi16) +
            (((size_t)(g * 8 + hp * 2 + hd)) * 32 + row) * 64 + q * 8;
        cp16(sb + hd * AT_HEAD_B + 20480 + prec * 4608 + row * 144 + q * 16, src);
    }
    CP_COMMIT();
    float* pe_s = (float*)(smem + AT_PE_OFF);
    for (int i = tid; i < 450; i += 256) {
        const int hd = i / 225, j = i - hd * 225;
        pe_s[hd * 240 + j] = pos_enc[(hp * 2 + hd) * 225 + j];
    }
    CP_WAIT(0);
    __syncthreads();

    const int hd = wid >> 2;
    const int wq = wid & 3;
    const int h  = hp * 2 + hd;
    const uint32_t hb = sb + hd * AT_HEAD_B;
    const float* pe = pe_s + hd * 240;

    const int a_off  = ((lane & 7) + ((lane >> 3) & 1) * 8) * 80 + (lane >> 4) * 16;
    const int b_off  = ((lane & 7) + ((lane >> 3) >> 1) * 8) * 80 + ((lane >> 3) & 1) * 16;
    const int vb_off = ((lane & 7) + ((lane >> 3) >> 1) * 8) * 144 + ((lane >> 3) & 1) * 16;

    float sacc[8][4];
#pragma unroll
    for (int j = 0; j < 8; j++)
#pragma unroll
        for (int e = 0; e < 4; e++) sacc[j][e] = 0.f;

#pragma unroll
    for (int ks = 0; ks < 2; ks++) {
        uint32_t ah[4], al[4];
        const uint32_t ad = hb + (wq * 16) * 80 + ks * 32 + a_off;
        LDM4(ah, ad);
        LDM4(al, ad + 5120);
#pragma unroll
        for (int ntk = 0; ntk < 4; ntk++) {
            uint32_t bh[4], bl[4];
            const uint32_t bd = hb + 10240 + (ntk * 16) * 80 + ks * 32 + b_off;
            LDM4(bh, bd);
            LDM4(bl, bd + 5120);
#pragma unroll
            for (int sub = 0; sub < 2; sub++) {
                float* c = sacc[ntk * 2 + sub];
                MMA16816(c, ah, bh[2 * sub], bh[2 * sub + 1]);
                MMA16816(c, ah, bl[2 * sub], bl[2 * sub + 1]);
                MMA16816(c, al, bh[2 * sub], bh[2 * sub + 1]);
            }
        }
    }

    const int w  = g & 63;
    const int wy = w >> 3, wx = w & 7;
    const bool eY = (wy == 7), eX = (wx == 7);
    const int R  = wq * 16 + (lane >> 2);
    const int ty0 = R >> 3,       tx0 = R & 7;
    const int ty1 = (R + 8) >> 3, tx1 = (R + 8) & 7;
    const int rq0 = (eY ? ((ty0 < 4) ? 1 : 2) : 0) * 3 + (eX ? ((tx0 < 4) ? 1 : 2) : 0);
    const int rq1 = (eY ? ((ty1 < 4) ? 1 : 2) : 0) * 3 + (eX ? ((tx1 < 4) ? 1 : 2) : 0);

#pragma unroll
    for (int j = 0; j < 8; j++) {
#pragma unroll
        for (int e = 0; e < 2; e++) {
            const int n  = j * 8 + (lane & 3) * 2 + e;
            const int ky = n >> 3, kx = n & 7;
            const int rk = (eY ? ((ky < 4) ? 1 : 2) : 0) * 3 + (eX ? ((kx < 4) ? 1 : 2) : 0);
            sacc[j][e]     = (rk != rq0) ? -1e30f
                : (sacc[j][e]     * SCALE_F + pe[(ty0 - ky + 7) * 15 + (tx0 - kx + 7)]);
            sacc[j][e + 2] = (rk != rq1) ? -1e30f
                : (sacc[j][e + 2] * SCALE_F + pe[(ty1 - ky + 7) * 15 + (tx1 - kx + 7)]);
        }
    }

    float m0 = -1e30f, m1 = -1e30f;
#pragma unroll
    for (int j = 0; j < 8; j++) {
        m0 = fmaxf(m0, fmaxf(sacc[j][0], sacc[j][1]));
        m1 = fmaxf(m1, fmaxf(sacc[j][2], sacc[j][3]));
    }
    m0 = fmaxf(m0, __shfl_xor_sync(0xffffffffu, m0, 1));
    m0 = fmaxf(m0, __shfl_xor_sync(0xffffffffu, m0, 2));
    m1 = fmaxf(m1, __shfl_xor_sync(0xffffffffu, m1, 1));
    m1 = fmaxf(m1, __shfl_xor_sync(0xffffffffu, m1, 2));
    float s0 = 0.f, s1 = 0.f;
#pragma unroll
    for (int j = 0; j < 8; j++) {
        sacc[j][0] = __expf(sacc[j][0] - m0); s0 += sacc[j][0];
        sacc[j][1] = __expf(sacc[j][1] - m0); s0 += sacc[j][1];
        sacc[j][2] = __expf(sacc[j][2] - m1); s1 += sacc[j][2];
        sacc[j][3] = __expf(sacc[j][3] - m1); s1 += sacc[j][3];
    }
    s0 += __shfl_xor_sync(0xffffffffu, s0, 1);
    s0 += __shfl_xor_sync(0xffffffffu, s0, 2);
    s1 += __shfl_xor_sync(0xffffffffu, s1, 1);
    s1 += __shfl_xor_sync(0xffffffffu, s1, 2);
    const float inv0 = 1.f / s0, inv1 = 1.f / s1;

    uint32_t pa[4][4], pl[4][4];
#pragma unroll
    for (int s = 0; s < 4; s++) {
        const int j0 = 2 * s, j1 = 2 * s + 1;
        const float p00 = sacc[j0][0] * inv0, p01 = sacc[j0][1] * inv0;
        const float p02 = sacc[j0][2] * inv1, p03 = sacc[j0][3] * inv1;
        const float p10 = sacc[j1][0] * inv0, p11 = sacc[j1][1] * inv0;
        const float p12 = sacc[j1][2] * inv1, p13 = sacc[j1][3] * inv1;
        pa[s][0] = pack2(p00, p01);  pa[s][1] = pack2(p02, p03);
        pa[s][2] = pack2(p10, p11);  pa[s][3] = pack2(p12, p13);
        pl[s][0] = pack2(p00 - __bfloat162float(__float2bfloat16_rn(p00)),
                         p01 - __bfloat162float(__float2bfloat16_rn(p01)));
        pl[s][1] = pack2(p02 - __bfloat162float(__float2bfloat16_rn(p02)),
                         p03 - __bfloat162float(__float2bfloat16_rn(p03)));
        pl[s][2] = pack2(p10 - __bfloat162float(__float2bfloat16_rn(p10)),
                         p11 - __bfloat162float(__float2bfloat16_rn(p11)));
        pl[s][3] = pack2(p12 - __bfloat162float(__float2bfloat16_rn(p12)),
                         p13 - __bfloat162float(__float2bfloat16_rn(p13)));
    }

    float oacc[4][4];
#pragma unroll
    for (int j = 0; j < 4; j++)
#pragma unroll
        for (int e = 0; e < 4; e++) oacc[j][e] = 0.f;

#pragma unroll
    for (int ks = 0; ks < 4; ks++) {
        uint32_t vh[2][4], vl[2][4];
#pragma unroll
        for (int nt16 = 0; nt16 < 2; nt16++) {
            const uint32_t vd = hb + 20480 + (nt16 * 16) * 144 + ks * 32 + vb_off;
            LDM4(vh[nt16], vd);
            LDM4(vl[nt16], vd + 4608);
        }
#pragma unroll
        for (int nt8 = 0; nt8 < 4; nt8++) {
            float* c = oacc[nt8];
            const uint32_t b0h = vh[nt8 >> 1][2 * (nt8 & 1)], b1h = vh[nt8 >> 1][2 * (nt8 & 1) + 1];
            const uint32_t b0l = vl[nt8 >> 1][2 * (nt8 & 1)], b1l = vl[nt8 >> 1][2 * (nt8 & 1) + 1];
            MMA16816(c, pa[ks], b0h, b1h);
            MMA16816(c, pl[ks], b0h, b1h);
            MMA16816(c, pa[ks], b0l, b1l);
        }
    }

#pragma unroll
    for (int nt8 = 0; nt8 < 4; nt8++) {
        const int n = nt8 * 8 + (lane & 3) * 2;
#pragma unroll
        for (int half = 0; half < 2; half++) {
            const int row = R + half * 8;
            const float f0 = oacc[nt8][half * 2 + 0];
            const float f1 = oacc[nt8][half * 2 + 1];
            __nv_bfloat16 h0 = __float2bfloat16_rn(f0), h1 = __float2bfloat16_rn(f1);
            const size_t idx = ((size_t)(g * 64 + row)) * 128 + h * 16 + (n >> 1);
            g_xhi32[idx] = (uint32_t)__bfloat16_as_ushort(h0) |
                           ((uint32_t)__bfloat16_as_ushort(h1) << 16);
            g_xlo32[idx] = (uint32_t)bf_hi(f0 - __bfloat162float(h0)) |
                           ((uint32_t)bf_hi(f1 - __bfloat162float(h1)) << 16);
        }
    }
}

// ---------------------------------------------------------------------------
extern "C" void kernel_launch(void* const* d_in, const int* in_sizes, int n_in,
                              void* d_out, int out_size)
{
    const float* x       = (const float*)d_in[0];
    const float* w_qkv   = (const float*)d_in[1];
    const float* b_qkv   = (const float*)d_in[2];
    const float* w_out   = (const float*)d_in[3];
    const float* b_out   = (const float*)d_in[4];
    const float* pos_enc = (const float*)d_in[5];
    float* out = (float*)d_out;

    cudaFuncSetAttribute(gemm_big_kernel<0>, cudaFuncAttributeMaxDynamicSharedMemorySize, SMEM_BIG);
    cudaFuncSetAttribute(gemm_big_kernel<1>, cudaFuncAttributeMaxDynamicSharedMemorySize, SMEM_BIG);
    cudaFuncSetAttribute(attn_kernel, cudaFuncAttributeMaxDynamicSharedMemorySize, AT_SMEM);

    // 1) split x into bf16 hi/lo
    prep_x_kernel<<<32768, 256>>>((const float4*)x);
    // 2) split weights into bf16 hi/lo
    prep_w_kernel<<<1024, 256>>>(w_qkv, w_out);
    // 3) QKV projection (resident-A HMMA) -> bf16 hi/lo Q,K pairs + V^T
    gemm_big_kernel<0><<<1024, 256, SMEM_BIG>>>(b_qkv, nullptr);
    // 4) windowed attention (HMMA core, 3 CTAs/SM)
    attn_kernel<<<NWIN * 4, 256, AT_SMEM>>>(pos_enc);
    // 5) output projection (resident-A HMMA) + inverse-roll scatter
    gemm_big_kernel<1><<<1024, 256, SMEM_BIG>>>(b_out, out);
}

// round 14
// speedup vs baseline: 1.2934x; 1.2934x over previous
#include <cuda_runtime.h>
#include <cuda_bf16.h>
#include <cstdint>

// ---------------------------------------------------------------------------
// Problem constants
// ---------------------------------------------------------------------------
#define NWIN      2048
#define HEADS     8
#define WS2       64
#define HEAD_DIM  32
#define DIMC      256
#define SCALE_F   0.17677669529663687f

// Scratch (static device globals — allocation-free per harness rules)
__device__ unsigned int   g_xhi32[16777216];   // bf16 pairs of x / attn out [row][k/2]
__device__ unsigned int   g_xlo32[16777216];
__device__ unsigned int   g_qkhi[33554432];    // Q,K bf16-hi pairs [part][g][h][t][d/2]
__device__ unsigned short g_vthi16[33554432];  // V^T bf16 [g][h][d][t]
__device__ unsigned short g_vtlo16[33554432];
__device__ unsigned short g_wqhi[196608];      // w_qkv row-major bf16 hi/lo [768][256]
__device__ unsigned short g_wqlo[196608];
__device__ unsigned short g_wohi[65536];       // w_out  row-major bf16 hi/lo [256][256]
__device__ unsigned short g_wolo[65536];

// ---------------------------------------------------------------------------
// Helpers (plain-target PTX only: ldmatrix / mma.sync / cp.async)
// ---------------------------------------------------------------------------
__device__ __forceinline__ uint32_t smem_u32(const void* p) {
    uint32_t a;
    asm("{ .reg .u64 t; cvta.to.shared.u64 t, %1; cvt.u32.u64 %0, t; }" : "=r"(a) : "l"(p));
    return a;
}
__device__ __forceinline__ void cp16(uint32_t dst, const void* src) {
    asm volatile("cp.async.cg.shared.global [%0], [%1], 16;" :: "r"(dst), "l"(src));
}
#define CP_COMMIT()  asm volatile("cp.async.commit_group;")
#define CP_WAIT(n)   asm volatile("cp.async.wait_group %0;" :: "n"(n))

#define LDM4(r, addr) \
    asm volatile("ldmatrix.sync.aligned.m8n8.x4.shared.b16 {%0,%1,%2,%3}, [%4];" \
        : "=r"((r)[0]), "=r"((r)[1]), "=r"((r)[2]), "=r"((r)[3]) : "r"(addr))

#define MMA16816(c, a, b0, b1) \
    asm volatile("mma.sync.aligned.m16n8k16.row.col.f32.bf16.bf16.f32 " \
        "{%0,%1,%2,%3},{%4,%5,%6,%7},{%8,%9},{%0,%1,%2,%3};" \
        : "+f"((c)[0]), "+f"((c)[1]), "+f"((c)[2]), "+f"((c)[3]) \
        : "r"((a)[0]), "r"((a)[1]), "r"((a)[2]), "r"((a)[3]), "r"(b0), "r"(b1))

__device__ __forceinline__ unsigned short bf_hi(float f) {
    return __bfloat16_as_ushort(__float2bfloat16_rn(f));
}
__device__ __forceinline__ uint32_t pack2(float a, float b) {
    return (uint32_t)bf_hi(a) | ((uint32_t)bf_hi(b) << 16);
}

// ---------------------------------------------------------------------------
// prep_x: split fp32 -> bf16 hi/lo packed-pair arrays (4 floats/thread)
// ---------------------------------------------------------------------------
__global__ __launch_bounds__(256) void prep_x_kernel(const float4* __restrict__ x4)
{
    const int gid = blockIdx.x * 256 + threadIdx.x;   // 8,388,608
    const float4 v = x4[gid];
    __nv_bfloat16 h0 = __float2bfloat16_rn(v.x), h1 = __float2bfloat16_rn(v.y);
    __nv_bfloat16 h2 = __float2bfloat16_rn(v.z), h3 = __float2bfloat16_rn(v.w);
    uint2 H, L;
    H.x = (uint32_t)__bfloat16_as_ushort(h0) | ((uint32_t)__bfloat16_as_ushort(h1) << 16);
    H.y = (uint32_t)__bfloat16_as_ushort(h2) | ((uint32_t)__bfloat16_as_ushort(h3) << 16);
    L.x = (uint32_t)bf_hi(v.x - __bfloat162float(h0)) | ((uint32_t)bf_hi(v.y - __bfloat162float(h1)) << 16);
    L.y = (uint32_t)bf_hi(v.z - __bfloat162float(h2)) | ((uint32_t)bf_hi(v.w - __bfloat162float(h3)) << 16);
    ((uint2*)g_xhi32)[gid] = H;
    ((uint2*)g_xlo32)[gid] = L;
}

// ---------------------------------------------------------------------------
// prep_w: weights -> row-major bf16 hi/lo
// ---------------------------------------------------------------------------
__global__ __launch_bounds__(256) void prep_w_kernel(const float* __restrict__ wq,
                                                     const float* __restrict__ wo)
{
    const int idx = blockIdx.x * 256 + threadIdx.x;   // 262,144
    if (idx < 196608) {
        const float v = wq[idx];
        __nv_bfloat16 h = __float2bfloat16_rn(v);
        g_wqhi[idx] = __bfloat16_as_ushort(h);
        g_wqlo[idx] = bf_hi(v - __bfloat162float(h));
    } else {
        const int i2 = idx - 196608;
        const float v = wo[i2];
        __nv_bfloat16 h = __float2bfloat16_rn(v);
        g_wohi[i2] = __bfloat16_as_ushort(h);
        g_wolo[i2] = bf_hi(v - __bfloat162float(h));
    }
}

// ---------------------------------------------------------------------------
// HMMA GEMM (R10-proven structure): block [128x128], K=256 in 8 chunks,
// cp.async double-buffered.
// MODE 0: Q/K tiles (nt 0..3), ONE-term bf16 (Ahi*Bhi), epilogue -> g_qkhi only
// MODE 2: V tiles (nt 4..5),   3-term, epilogue -> transposed V hi/lo
// MODE 1: out-proj,            3-term, epilogue -> d_out (inverse-roll scatter)
// ---------------------------------------------------------------------------
#define TILE_B    10240               // 128*80

template <int MODE>
__global__ __launch_bounds__(256)
void gemm_mma_kernel(const float* __restrict__ bias, float* __restrict__ out)
{
    constexpr bool ONE  = (MODE == 0);
    constexpr int  BUFB = ONE ? (2 * TILE_B) : (4 * TILE_B);
    constexpr int  BHI  = ONE ? TILE_B : (2 * TILE_B);
    extern __shared__ char smem[];
    __shared__ int   rowoff[128];
    __shared__ float bias_s[128];

    const uint32_t sb  = smem_u32(smem);
    const int tid  = threadIdx.x;
    const int wid  = tid >> 5;
    const int lane = tid & 31;
    const int nt = (MODE == 2) ? (blockIdx.x + 4) : blockIdx.x;
    const int mb = blockIdx.y;

    if (tid < 128) {
        const int r = tid;
        const int g = mb * 2 + (r >> 6);
        const int b = g >> 6, w = g & 63;
        const int wy = w >> 3, wx = w & 7, ty = (r >> 3) & 7, tx = r & 7;
        const int i_ = (wy * 8 + ty + 4) & 63;
        const int j_ = (wx * 8 + tx + 4) & 63;
        const int srcRow = b * 4096 + i_ * 64 + j_;
        rowoff[r] = (MODE == 1) ? srcRow * 256 : srcRow * 128;
        bias_s[r] = bias[nt * 128 + r];
    }
    __syncthreads();

    const unsigned short* wh = (MODE == 1) ? g_wohi : g_wqhi;
    const unsigned short* wl = (MODE == 1) ? g_wolo : g_wqlo;

    const int lrow = tid >> 1;
    const int q0   = (tid & 1) * 2;
    const int aRowBase = (MODE == 1) ? (mb * 128 + lrow) * 128 : rowoff[lrow];
    const int bRowBase = (nt * 128 + lrow) * 256;

    float acc[2][8][4];
#pragma unroll
    for (int i = 0; i < 2; i++)
#pragma unroll
        for (int j = 0; j < 8; j++)
#pragma unroll
            for (int e = 0; e < 4; e++) acc[i][j][e] = 0.f;

    const int a_off = ((lane & 7) + ((lane >> 3) & 1) * 8) * 80 + (lane >> 4) * 16;
    const int b_off = ((lane & 7) + ((lane >> 3) >> 1) * 8) * 80 + ((lane >> 3) & 1) * 16;
    const int wr = wid & 3;
    const int wc = wid >> 2;

#define LOAD_CHUNK(kc, buf) do { \
    const uint32_t base = sb + (buf) * BUFB + lrow * 80; \
    _Pragma("unroll") \
    for (int j = 0; j < 2; j++) { \
        const int q = q0 + j; \
        const uint32_t d = base + q * 16; \
        cp16(d,       g_xhi32 + aRowBase + (kc) * 16 + q * 4); \
        cp16(d + BHI, wh + bRowBase + (kc) * 32 + q * 8); \
        if (!ONE) { \
            cp16(d + TILE_B,     g_xlo32 + aRowBase + (kc) * 16 + q * 4); \
            cp16(d + 3 * TILE_B, wl + bRowBase + (kc) * 32 + q * 8); \
        } \
    } \
} while (0)

    LOAD_CHUNK(0, 0);
    CP_COMMIT();

    for (int kc = 0; kc < 8; kc++) {
        if (kc < 7) {
            LOAD_CHUNK(kc + 1, (kc + 1) & 1);
            CP_COMMIT();
            CP_WAIT(1);
        } else {
            CP_WAIT(0);
        }
        __syncthreads();

        const uint32_t Ab = sb + (kc & 1) * BUFB;
        const uint32_t Bb = Ab + BHI;
#pragma unroll
        for (int ks = 0; ks < 2; ks++) {
            uint32_t ah[2][4], al[2][4];
#pragma unroll
            for (int mt = 0; mt < 2; mt++) {
                const uint32_t ad = Ab + (wr * 32 + mt * 16) * 80 + ks * 32 + a_off;
                LDM4(ah[mt], ad);
                if (!ONE) LDM4(al[mt], ad + TILE_B);
            }
#pragma unroll
            for (int np = 0; np < 4; np++) {
                uint32_t bh[4], bl[4];
                const uint32_t bd = Bb + (wc * 64 + np * 16) * 80 + ks * 32 + b_off;
                LDM4(bh, bd);
                if (!ONE) LDM4(bl, bd + TILE_B);
#pragma unroll
                for (int mt = 0; mt < 2; mt++) {
#pragma unroll
                    for (int sub = 0; sub < 2; sub++) {
                        float* c = acc[mt][np * 2 + sub];
                        MMA16816(c, ah[mt], bh[2 * sub], bh[2 * sub + 1]);
                        if (!ONE) {
                            MMA16816(c, ah[mt], bl[2 * sub], bl[2 * sub + 1]);
                            MMA16816(c, al[mt], bh[2 * sub], bh[2 * sub + 1]);
                        }
                    }
                }
            }
        }
        __syncthreads();
    }

#pragma unroll
    for (int mt = 0; mt < 2; mt++) {
        const int R0 = wr * 32 + mt * 16 + (lane >> 2);
#pragma unroll
        for (int nti = 0; nti < 8; nti++) {
            const int cb = wc * 64 + nti * 8 + (lane & 3) * 2;
            const float bz0 = bias_s[cb], bz1 = bias_s[cb + 1];
            const float* c = acc[mt][nti];
#pragma unroll
            for (int half = 0; half < 2; half++) {
                const int R = R0 + half * 8;
                const float vx = c[half * 2 + 0] + bz0;
                const float vy = c[half * 2 + 1] + bz1;
                if (MODE == 0) {
                    // Q,K: bf16-hi only
                    const int nn   = nt * 128 + cb;
                    const int part = nn >> 8;          // 0 or 1
                    const int h    = (nn & 255) >> 5;
                    const int d    = nn & 31;
                    const int g    = mb * 2 + (R >> 6);
                    const int t    = R & 63;
                    const size_t idx = (size_t)part * 16777216 +
                        (((size_t)(g * 8 + h)) * 64 + t) * 16 + (d >> 1);
                    g_qkhi[idx] = pack2(vx, vy);
                } else if (MODE == 2) {
                    // V: transposed, hi/lo
                    const int nn = nt * 128 + cb;      // 512..767
                    const int h  = (nn & 255) >> 5;
                    const int d  = nn & 31;
                    const int g  = mb * 2 + (R >> 6);
                    const int t  = R & 63;
                    __nv_bfloat16 h0 = __float2bfloat16_rn(vx);
                    __nv_bfloat16 h1 = __float2bfloat16_rn(vy);
                    const size_t bidx = (((size_t)(g * 8 + h)) * 32 + d) * 64 + t;
                    g_vthi16[bidx]      = __bfloat16_as_ushort(h0);
                    g_vthi16[bidx + 64] = __bfloat16_as_ushort(h1);
                    g_vtlo16[bidx]      = bf_hi(vx - __bfloat162float(h0));
                    g_vtlo16[bidx + 64] = bf_hi(vy - __bfloat162float(h1));
                } else {
                    float2 v;
                    v.x = vx; v.y = vy;
                    *(float2*)(out + rowoff[R] + nt * 128 + cb) = v;
                }
            }
        }
    }
#undef LOAD_CHUNK
}

// ---------------------------------------------------------------------------
// Attention core (HMMA): block = 256 thr = 2 heads x 4 warps, 3 CTAs/SM.
// S = Qhi Khi^T (1-term — logits are small, absolute error ~3e-4 suffices),
// softmax, P split bf16 hi/lo in-register, PV 3-term with V^T hi/lo.
// smem per head: Qhi 5120 | Khi 5120 | Vhi 4608 | Vlo 4608 = 19456 B.
// ---------------------------------------------------------------------------
#define AT_HEAD_B   19456
#define AT_PE_OFF   38912
#define AT_SMEM     40960

__global__ __launch_bounds__(256, 3)
void attn_kernel(const float* __restrict__ pos_enc)
{
    extern __shared__ char smem[];
    const uint32_t sb = smem_u32(smem);
    const int tid  = threadIdx.x;
    const int wid  = tid >> 5;
    const int lane = tid & 31;

    const int g  = blockIdx.x >> 2;
    const int hp = blockIdx.x & 3;

    // ---- stage Q hi, K hi ----
#pragma unroll
    for (int it = 0; it < 4; it++) {
        const int i = tid + it * 256;           // 0..1023
        const int hd  = i >> 9;
        const int qk  = (i >> 8) & 1;           // 0:Q 1:K
        const int row = (i >> 2) & 63;
        const int q16 = i & 3;
        const unsigned int* src = g_qkhi + (size_t)qk * 16777216 +
            (((size_t)(g * 8 + hp * 2 + hd)) * 64 + row) * 16 + q16 * 4;
        cp16(sb + hd * AT_HEAD_B + qk * 5120 + row * 80 + q16 * 16, src);
    }
    // ---- stage V^T hi/lo ----
#pragma unroll
    for (int it = 0; it < 4; it++) {
        const int i = tid + it * 256;           // 0..1023
        const int hd   = i >> 9;
        const int prec = (i >> 8) & 1;
        const int row  = (i >> 3) & 31;
        const int q    = i & 7;
        const unsigned short* src = (prec ? g_vtlo16 : g_vthi16) +
            (((size_t)(g * 8 + hp * 2 + hd)) * 32 + row) * 64 + q * 8;
        cp16(sb + hd * AT_HEAD_B + 10240 + prec * 4608 + row * 144 + q * 16, src);
    }
    CP_COMMIT();
    float* pe_s = (float*)(smem + AT_PE_OFF);
    for (int i = tid; i < 450; i += 256) {
        const int hd = i / 225, j = i - hd * 225;
        pe_s[hd * 240 + j] = pos_enc[(hp * 2 + hd) * 225 + j];
    }
    CP_WAIT(0);
    __syncthreads();

    const int hd = wid >> 2;
    const int wq = wid & 3;
    const int h  = hp * 2 + hd;
    const uint32_t hb = sb + hd * AT_HEAD_B;
    const float* pe = pe_s + hd * 240;

    const int a_off  = ((lane & 7) + ((lane >> 3) & 1) * 8) * 80 + (lane >> 4) * 16;
    const int b_off  = ((lane & 7) + ((lane >> 3) >> 1) * 8) * 80 + ((lane >> 3) & 1) * 16;
    const int vb_off = ((lane & 7) + ((lane >> 3) >> 1) * 8) * 144 + ((lane >> 3) & 1) * 16;

    // ---- S = Q K^T (1-term) ----
    float sacc[8][4];
#pragma unroll
    for (int j = 0; j < 8; j++)
#pragma unroll
        for (int e = 0; e < 4; e++) sacc[j][e] = 0.f;

#pragma unroll
    for (int ks = 0; ks < 2; ks++) {
        uint32_t ah[4];
        LDM4(ah, hb + (wq * 16) * 80 + ks * 32 + a_off);
#pragma unroll
        for (int ntk = 0; ntk < 4; ntk++) {
            uint32_t bh[4];
            LDM4(bh, hb + 5120 + (ntk * 16) * 80 + ks * 32 + b_off);
#pragma unroll
            for (int sub = 0; sub < 2; sub++)
                MMA16816(sacc[ntk * 2 + sub], ah, bh[2 * sub], bh[2 * sub + 1]);
        }
    }

    const int w  = g & 63;
    const int wy = w >> 3, wx = w & 7;
    const bool eY = (wy == 7), eX = (wx == 7);
    const int R  = wq * 16 + (lane >> 2);
    const int ty0 = R >> 3,       tx0 = R & 7;
    const int ty1 = (R + 8) >> 3, tx1 = (R + 8) & 7;
    const int rq0 = (eY ? ((ty0 < 4) ? 1 : 2) : 0) * 3 + (eX ? ((tx0 < 4) ? 1 : 2) : 0);
    const int rq1 = (eY ? ((ty1 < 4) ? 1 : 2) : 0) * 3 + (eX ? ((tx1 < 4) ? 1 : 2) : 0);

#pragma unroll
    for (int j = 0; j < 8; j++) {
#pragma unroll
        for (int e = 0; e < 2; e++) {
            const int n  = j * 8 + (lane & 3) * 2 + e;
            const int ky = n >> 3, kx = n & 7;
            const int rk = (eY ? ((ky < 4) ? 1 : 2) : 0) * 3 + (eX ? ((kx < 4) ? 1 : 2) : 0);
            sacc[j][e]     = (rk != rq0) ? -1e30f
                : (sacc[j][e]     * SCALE_F + pe[(ty0 - ky + 7) * 15 + (tx0 - kx + 7)]);
            sacc[j][e + 2] = (rk != rq1) ? -1e30f
                : (sacc[j][e + 2] * SCALE_F + pe[(ty1 - ky + 7) * 15 + (tx1 - kx + 7)]);
        }
    }

    float m0 = -1e30f, m1 = -1e30f;
#pragma unroll
    for (int j = 0; j < 8; j++) {
        m0 = fmaxf(m0, fmaxf(sacc[j][0], sacc[j][1]));
        m1 = fmaxf(m1, fmaxf(sacc[j][2], sacc[j][3]));
    }
    m0 = fmaxf(m0, __shfl_xor_sync(0xffffffffu, m0, 1));
    m0 = fmaxf(m0, __shfl_xor_sync(0xffffffffu, m0, 2));
    m1 = fmaxf(m1, __shfl_xor_sync(0xffffffffu, m1, 1));
    m1 = fmaxf(m1, __shfl_xor_sync(0xffffffffu, m1, 2));
    float s0 = 0.f, s1 = 0.f;
#pragma unroll
    for (int j = 0; j < 8; j++) {
        sacc[j][0] = __expf(sacc[j][0] - m0); s0 += sacc[j][0];
        sacc[j][1] = __expf(sacc[j][1] - m0); s0 += sacc[j][1];
        sacc[j][2] = __expf(sacc[j][2] - m1); s1 += sacc[j][2];
        sacc[j][3] = __expf(sacc[j][3] - m1); s1 += sacc[j][3];
    }
    s0 += __shfl_xor_sync(0xffffffffu, s0, 1);
    s0 += __shfl_xor_sync(0xffffffffu, s0, 2);
    s1 += __shfl_xor_sync(0xffffffffu, s1, 1);
    s1 += __shfl_xor_sync(0xffffffffu, s1, 2);
    const float inv0 = 1.f / s0, inv1 = 1.f / s1;

    // ---- P -> bf16 hi/lo A-frags (in-register repack) ----
    uint32_t pa[4][4], pl[4][4];
#pragma unroll
    for (int s = 0; s < 4; s++) {
        const int j0 = 2 * s, j1 = 2 * s + 1;
        const float p00 = sacc[j0][0] * inv0, p01 = sacc[j0][1] * inv0;
        const float p02 = sacc[j0][2] * inv1, p03 = sacc[j0][3] * inv1;
        const float p10 = sacc[j1][0] * inv0, p11 = sacc[j1][1] * inv0;
        const float p12 = sacc[j1][2] * inv1, p13 = sacc[j1][3] * inv1;
        pa[s][0] = pack2(p00, p01);  pa[s][1] = pack2(p02, p03);
        pa[s][2] = pack2(p10, p11);  pa[s][3] = pack2(p12, p13);
        pl[s][0] = pack2(p00 - __bfloat162float(__float2bfloat16_rn(p00)),
                         p01 - __bfloat162float(__float2bfloat16_rn(p01)));
        pl[s][1] = pack2(p02 - __bfloat162float(__float2bfloat16_rn(p02)),
                         p03 - __bfloat162float(__float2bfloat16_rn(p03)));
        pl[s][2] = pack2(p10 - __bfloat162float(__float2bfloat16_rn(p10)),
                         p11 - __bfloat162float(__float2bfloat16_rn(p11)));
        pl[s][3] = pack2(p12 - __bfloat162float(__float2bfloat16_rn(p12)),
                         p13 - __bfloat162float(__float2bfloat16_rn(p13)));
    }

    // ---- O = P V (3-term, V^T fragments) ----
    float oacc[4][4];
#pragma unroll
    for (int j = 0; j < 4; j++)
#pragma unroll
        for (int e = 0; e < 4; e++) oacc[j][e] = 0.f;

#pragma unroll
    for (int ks = 0; ks < 4; ks++) {
        uint32_t vh[2][4], vl[2][4];
#pragma unroll
        for (int nt16 = 0; nt16 < 2; nt16++) {
            const uint32_t vd = hb + 10240 + (nt16 * 16) * 144 + ks * 32 + vb_off;
            LDM4(vh[nt16], vd);
            LDM4(vl[nt16], vd + 4608);
        }
#pragma unroll
        for (int nt8 = 0; nt8 < 4; nt8++) {
            float* c = oacc[nt8];
            const uint32_t b0h = vh[nt8 >> 1][2 * (nt8 & 1)], b1h = vh[nt8 >> 1][2 * (nt8 & 1) + 1];
            const uint32_t b0l = vl[nt8 >> 1][2 * (nt8 & 1)], b1l = vl[nt8 >> 1][2 * (nt8 & 1) + 1];
            MMA16816(c, pa[ks], b0h, b1h);
            MMA16816(c, pl[ks], b0h, b1h);
            MMA16816(c, pa[ks], b0l, b1l);
        }
    }

    // ---- epilogue: bf16 hi/lo split of O ----
#pragma unroll
    for (int nt8 = 0; nt8 < 4; nt8++) {
        const int n = nt8 * 8 + (lane & 3) * 2;
#pragma unroll
        for (int half = 0; half < 2; half++) {
            const int row = R + half * 8;
            const float f0 = oacc[nt8][half * 2 + 0];
            const float f1 = oacc[nt8][half * 2 + 1];
            __nv_bfloat16 h0 = __float2bfloat16_rn(f0), h1 = __float2bfloat16_rn(f1);
            const size_t idx = ((size_t)(g * 64 + row)) * 128 + h * 16 + (n >> 1);
            g_xhi32[idx] = (uint32_t)__bfloat16_as_ushort(h0) |
                           ((uint32_t)__bfloat16_as_ushort(h1) << 16);
            g_xlo32[idx] = (uint32_t)bf_hi(f0 - __bfloat162float(h0)) |
                           ((uint32_t)bf_hi(f1 - __bfloat162float(h1)) << 16);
        }
    }
}

// ---------------------------------------------------------------------------
extern "C" void kernel_launch(void* const* d_in, const int* in_sizes, int n_in,
                              void* d_out, int out_size)
{
    const float* x       = (const float*)d_in[0];
    const float* w_qkv   = (const float*)d_in[1];
    const float* b_qkv   = (const float*)d_in[2];
    const float* w_out   = (const float*)d_in[3];
    const float* b_out   = (const float*)d_in[4];
    const float* pos_enc = (const float*)d_in[5];
    float* out = (float*)d_out;

    cudaFuncSetAttribute(gemm_mma_kernel<0>, cudaFuncAttributeMaxDynamicSharedMemorySize, 2 * 2 * TILE_B);
    cudaFuncSetAttribute(gemm_mma_kernel<2>, cudaFuncAttributeMaxDynamicSharedMemorySize, 2 * 4 * TILE_B);
    cudaFuncSetAttribute(gemm_mma_kernel<1>, cudaFuncAttributeMaxDynamicSharedMemorySize, 2 * 4 * TILE_B);
    cudaFuncSetAttribute(attn_kernel, cudaFuncAttributeMaxDynamicSharedMemorySize, AT_SMEM);

    // 1) split x into bf16 hi/lo
    prep_x_kernel<<<32768, 256>>>((const float4*)x);
    // 2) split weights into bf16 hi/lo
    prep_w_kernel<<<1024, 256>>>(w_qkv, w_out);
    // 3a) Q,K projection (1-term bf16) -> g_qkhi
    gemm_mma_kernel<0><<<dim3(4, 1024), 256, 2 * 2 * TILE_B>>>(b_qkv, nullptr);
    // 3b) V projection (3-term bf16) -> transposed V hi/lo
    gemm_mma_kernel<2><<<dim3(2, 1024), 256, 2 * 4 * TILE_B>>>(b_qkv, nullptr);
    // 4) windowed attention (1-term S, 3-term PV)
    attn_kernel<<<NWIN * 4, 256, AT_SMEM>>>(pos_enc);
    // 5) output projection (3-term) + inverse-roll scatter
    gemm_mma_kernel<1><<<dim3(2, 1024), 256, 2 * 4 * TILE_B>>>(b_out, out);
}